// round 8
// baseline (speedup 1.0000x reference)
#include <cuda_runtime.h>
#include <stdint.h>

// Polar encoder, N=1024, K=512. Fused single kernel, 2 rows per warp per CTA
// (doubled read MLP vs R5; loads for both rows front-batched).
// Pack: coalesced scalar loads + ballot. Bit mapping: p = j*128 + 4*lane + b
// <-> lane reg bit (4j+b): stages {0,1,7,8,9} in-register, {2..6} shfl_xor,
// epilogue float4 stores straight from the lane's own register.

#define PN 1024
#define PK 512
#define WARPS_PER_CTA 16
#define CTA_THREADS (32 * WARPS_PER_CTA)
#define ROWS_PER_CTA (2 * WARPS_PER_CTA)

__device__ __forceinline__ unsigned butterfly(unsigned x, int lane) {
    x ^= (x >> 1)  & 0x55555555u;   // s=0
    x ^= (x >> 2)  & 0x33333333u;   // s=1
    x ^= (x >> 4)  & 0x0f0f0f0fu;   // s=7
    x ^= (x >> 8)  & 0x00ff00ffu;   // s=8
    x ^= (x >> 16) & 0x0000ffffu;   // s=9
#pragma unroll
    for (int d = 1; d <= 16; d <<= 1) {           // s=2..6 (lane bits)
        unsigned y = __shfl_xor_sync(0xffffffffu, x, d);
        if ((lane & d) == 0) x ^= y;
    }
    return x;
}

__device__ __forceinline__ void store_row(float* __restrict__ out, int row,
                                          int lane, unsigned x) {
    float4* op = (float4*)(out + (size_t)row * PN);
#pragma unroll
    for (int j = 0; j < 8; j++) {
        unsigned n = x >> (4 * j);
        float4 f;
        f.x = __uint_as_float((n & 1u)        * 0x3f800000u);
        f.y = __uint_as_float(((n >> 1) & 1u) * 0x3f800000u);
        f.z = __uint_as_float(((n >> 2) & 1u) * 0x3f800000u);
        f.w = __uint_as_float(((n >> 3) & 1u) * 0x3f800000u);
        __stcs(op + j * 32 + lane, f);
    }
}

__global__ __launch_bounds__(CTA_THREADS)
void polar_encode_kernel(const float* __restrict__ u,
                         const int*   __restrict__ info_pos,
                         float* __restrict__ out,
                         int batch, int kcount) {
    const int tid  = threadIdx.x;
    const int lane = tid & 31;
    const int warp = tid >> 5;

    __shared__ int s_fast;
    __shared__ int s_inv[PN];                             // general path only
    __shared__ unsigned s_ubits[WARPS_PER_CTA][2][17];

    // ---- per-CTA fast-layout check: kcount==512 && info_pos[k]==512+k ----
    if (tid == 0) s_fast = (kcount == PK) ? 1 : 0;
    __syncthreads();
    const int frozen = PN - kcount;
    if (tid < kcount) {                                   // kcount<=512
        if (info_pos[tid] != frozen + tid) s_fast = 0;    // benign race
    }
    __syncthreads();
    const int fast = s_fast;

    if (!fast) {
        for (int i = tid; i < PN; i += CTA_THREADS) s_inv[i] = -1;
        __syncthreads();
        for (int k = tid; k < kcount; k += CTA_THREADS) s_inv[info_pos[k]] = k;
        __syncthreads();
    }

    const int r0 = blockIdx.x * ROWS_PER_CTA + warp;
    const int r1 = r0 + WARPS_PER_CTA;
    const bool ok0 = (r0 < batch);           // warp-uniform
    const bool ok1 = (r1 < batch);           // warp-uniform

    if (fast) {
        // ---- front-batch all loads for both rows ----
        float va[16], vb[16];
        const float* ua = u + (size_t)r0 * PK;
        const float* ub = u + (size_t)r1 * PK;
        if (ok0) {
#pragma unroll
            for (int j = 0; j < 16; j++) va[j] = __ldcs(ua + j * 32 + lane);
        }
        if (ok1) {
#pragma unroll
            for (int j = 0; j < 16; j++) vb[j] = __ldcs(ub + j * 32 + lane);
        }

        // ---- ballots -> smem words ----
        if (ok0) {
#pragma unroll
            for (int j = 0; j < 16; j++) {
                unsigned b = __ballot_sync(0xffffffffu, va[j] != 0.0f);
                if (lane == j) s_ubits[warp][0][j] = b;
            }
        }
        if (ok1) {
#pragma unroll
            for (int j = 0; j < 16; j++) {
                unsigned b = __ballot_sync(0xffffffffu, vb[j] != 0.0f);
                if (lane == j) s_ubits[warp][1][j] = b;
            }
        }
        __syncwarp();

        // reg bit r = 16+4i+b <- info bit k = i*128 + 4*lane + b
        // ballot word w = 4i + (lane>>3); nibble at 4*(lane&7)
        const int wsel = lane >> 3;
        const int bsel = (lane & 7) * 4;

        if (ok0) {
            unsigned x = 0u;
#pragma unroll
            for (int i = 0; i < 4; i++) {
                unsigned n = (s_ubits[warp][0][4 * i + wsel] >> bsel) & 0xfu;
                x |= n << (16 + 4 * i);
            }
            x = butterfly(x, lane);
            store_row(out, r0, lane, x);
        }
        if (ok1) {
            unsigned x = 0u;
#pragma unroll
            for (int i = 0; i < 4; i++) {
                unsigned n = (s_ubits[warp][1][4 * i + wsel] >> bsel) & 0xfu;
                x |= n << (16 + 4 * i);
            }
            x = butterfly(x, lane);
            store_row(out, r1, lane, x);
        }
    } else {
        // ---- general scatter path: per-row ballot pack + inverse map ----
#pragma unroll
        for (int h = 0; h < 2; h++) {
            int row = (h == 0) ? r0 : r1;
            if (row >= batch) continue;
            const float* up = u + (size_t)row * PK;
            const int nwords = (kcount + 31) >> 5;
            for (int j = 0; j < nwords; j++) {
                int idx = j * 32 + lane;
                float v = (idx < kcount) ? __ldcs(up + idx) : 0.0f;
                unsigned b = __ballot_sync(0xffffffffu, v != 0.0f);
                if (lane == j) s_ubits[warp][0][j & 15] = b;
            }
            __syncwarp();
            unsigned x = 0u;
#pragma unroll 4
            for (int r = 0; r < 32; r++) {
                int j = r >> 2, b = r & 3;
                int p = j * 128 + lane * 4 + b;
                int k = s_inv[p];
                if (k >= 0)
                    x |= ((s_ubits[warp][0][k >> 5] >> (k & 31)) & 1u) << r;
            }
            x = butterfly(x, lane);
            store_row(out, row, lane, x);
            __syncwarp();
        }
    }
}

extern "C" void kernel_launch(void* const* d_in, const int* in_sizes, int n_in,
                              void* d_out, int out_size) {
    const float* u        = (const float*)d_in[0];
    const int*   info_pos = (const int*)d_in[1];
    // d_in[2] = ind_gather: butterfly structure fixed by N; unused.

    const int kcount = in_sizes[1];              // 512
    const int batch  = in_sizes[0] / kcount;     // 65536
    float* out = (float*)d_out;

    int ctas = (batch + ROWS_PER_CTA - 1) / ROWS_PER_CTA;
    polar_encode_kernel<<<ctas, CTA_THREADS>>>(u, info_pos, out, batch, kcount);
}

// round 9
// speedup vs baseline: 1.0039x; 1.0039x over previous
#include <cuda_runtime.h>
#include <stdint.h>

// Polar encoder, N=1024, K=512. Fused kernel, block 256, 2 rows per warp with
// all 32 loads front-batched and enough registers to hold them (no tight
// launch-bounds cap). Pack: coalesced scalar loads + ballot.
// Bit mapping: p = j*128 + 4*lane + b <-> lane reg bit (4j+b):
// stages {0,1,7,8,9} in-register, {2..6} shfl_xor, float4 stores.

#define PN 1024
#define PK 512
#define WARPS_PER_CTA 8
#define CTA_THREADS (32 * WARPS_PER_CTA)
#define ROWS_PER_CTA (2 * WARPS_PER_CTA)

__device__ __forceinline__ unsigned butterfly(unsigned x, int lane) {
    x ^= (x >> 1)  & 0x55555555u;   // s=0
    x ^= (x >> 2)  & 0x33333333u;   // s=1
    x ^= (x >> 4)  & 0x0f0f0f0fu;   // s=7
    x ^= (x >> 8)  & 0x00ff00ffu;   // s=8
    x ^= (x >> 16) & 0x0000ffffu;   // s=9
#pragma unroll
    for (int d = 1; d <= 16; d <<= 1) {           // s=2..6 (lane bits)
        unsigned y = __shfl_xor_sync(0xffffffffu, x, d);
        if ((lane & d) == 0) x ^= y;
    }
    return x;
}

__device__ __forceinline__ void store_row(float* __restrict__ out, int row,
                                          int lane, unsigned x) {
    float4* op = (float4*)(out + (size_t)row * PN);
#pragma unroll
    for (int j = 0; j < 8; j++) {
        unsigned n = x >> (4 * j);
        float4 f;
        f.x = __uint_as_float((n & 1u)        * 0x3f800000u);
        f.y = __uint_as_float(((n >> 1) & 1u) * 0x3f800000u);
        f.z = __uint_as_float(((n >> 2) & 1u) * 0x3f800000u);
        f.w = __uint_as_float(((n >> 3) & 1u) * 0x3f800000u);
        __stcs(op + j * 32 + lane, f);
    }
}

__global__ __launch_bounds__(CTA_THREADS)
void polar_encode_kernel(const float* __restrict__ u,
                         const int*   __restrict__ info_pos,
                         float* __restrict__ out,
                         int batch, int kcount) {
    const int tid  = threadIdx.x;
    const int lane = tid & 31;
    const int warp = tid >> 5;

    __shared__ int s_fast;
    __shared__ int s_inv[PN];                             // general path only
    __shared__ unsigned s_ubits[WARPS_PER_CTA][2][17];

    // ---- per-CTA fast-layout check: kcount==512 && info_pos[k]==512+k ----
    if (tid == 0) s_fast = (kcount == PK) ? 1 : 0;
    __syncthreads();
    const int frozen = PN - kcount;
    for (int k = tid; k < kcount; k += CTA_THREADS) {
        if (info_pos[k] != frozen + k) s_fast = 0;        // benign race
    }
    __syncthreads();
    const int fast = s_fast;

    if (!fast) {
        for (int i = tid; i < PN; i += CTA_THREADS) s_inv[i] = -1;
        __syncthreads();
        for (int k = tid; k < kcount; k += CTA_THREADS) s_inv[info_pos[k]] = k;
        __syncthreads();
    }

    const int r0 = blockIdx.x * ROWS_PER_CTA + warp;
    const int r1 = r0 + WARPS_PER_CTA;
    const bool ok0 = (r0 < batch);            // warp-uniform
    const bool ok1 = (r1 < batch);            // warp-uniform

    if (fast) {
        // ---- front-batch all 32 loads (held in registers) ----
        float va[16], vb[16];
        const float* ua = u + (size_t)r0 * PK;
        const float* ub = u + (size_t)r1 * PK;
        if (ok0) {
#pragma unroll
            for (int j = 0; j < 16; j++) va[j] = __ldcs(ua + j * 32 + lane);
        }
        if (ok1) {
#pragma unroll
            for (int j = 0; j < 16; j++) vb[j] = __ldcs(ub + j * 32 + lane);
        }

        // ---- ballots -> smem words ----
        if (ok0) {
#pragma unroll
            for (int j = 0; j < 16; j++) {
                unsigned b = __ballot_sync(0xffffffffu, va[j] != 0.0f);
                if (lane == j) s_ubits[warp][0][j] = b;
            }
        }
        if (ok1) {
#pragma unroll
            for (int j = 0; j < 16; j++) {
                unsigned b = __ballot_sync(0xffffffffu, vb[j] != 0.0f);
                if (lane == j) s_ubits[warp][1][j] = b;
            }
        }
        __syncwarp();

        // reg bit r = 16+4i+b <- info bit k = i*128 + 4*lane + b
        // ballot word w = 4i + (lane>>3); nibble at 4*(lane&7)
        const int wsel = lane >> 3;
        const int bsel = (lane & 7) * 4;

        if (ok0) {
            unsigned x = 0u;
#pragma unroll
            for (int i = 0; i < 4; i++) {
                unsigned n = (s_ubits[warp][0][4 * i + wsel] >> bsel) & 0xfu;
                x |= n << (16 + 4 * i);
            }
            x = butterfly(x, lane);
            store_row(out, r0, lane, x);
        }
        if (ok1) {
            unsigned x = 0u;
#pragma unroll
            for (int i = 0; i < 4; i++) {
                unsigned n = (s_ubits[warp][1][4 * i + wsel] >> bsel) & 0xfu;
                x |= n << (16 + 4 * i);
            }
            x = butterfly(x, lane);
            store_row(out, r1, lane, x);
        }
    } else {
        // ---- general scatter path: per-row ballot pack + inverse map ----
#pragma unroll
        for (int h = 0; h < 2; h++) {
            int row = (h == 0) ? r0 : r1;
            if (row >= batch) continue;
            const float* up = u + (size_t)row * PK;
            const int nwords = (kcount + 31) >> 5;
            for (int j = 0; j < nwords; j++) {
                int idx = j * 32 + lane;
                float v = (idx < kcount) ? __ldcs(up + idx) : 0.0f;
                unsigned b = __ballot_sync(0xffffffffu, v != 0.0f);
                if (lane == j) s_ubits[warp][0][j & 15] = b;
            }
            __syncwarp();
            unsigned x = 0u;
#pragma unroll 4
            for (int r = 0; r < 32; r++) {
                int j = r >> 2, b = r & 3;
                int p = j * 128 + lane * 4 + b;
                int k = s_inv[p];
                if (k >= 0)
                    x |= ((s_ubits[warp][0][k >> 5] >> (k & 31)) & 1u) << r;
            }
            x = butterfly(x, lane);
            store_row(out, row, lane, x);
            __syncwarp();
        }
    }
}

extern "C" void kernel_launch(void* const* d_in, const int* in_sizes, int n_in,
                              void* d_out, int out_size) {
    const float* u        = (const float*)d_in[0];
    const int*   info_pos = (const int*)d_in[1];
    // d_in[2] = ind_gather: butterfly structure fixed by N; unused.

    const int kcount = in_sizes[1];              // 512
    const int batch  = in_sizes[0] / kcount;     // 65536
    float* out = (float*)d_out;

    int ctas = (batch + ROWS_PER_CTA - 1) / ROWS_PER_CTA;
    polar_encode_kernel<<<ctas, CTA_THREADS>>>(u, info_pos, out, batch, kcount);
}